// round 1
// baseline (speedup 1.0000x reference)
#include <cuda_runtime.h>

// ConvNeXt block: dwconv7x7 -> LN(channels) -> 1x1 MLP (128->512->128) -> residual
// N=32, C=128, H=W=64, D=512. fp32 throughout.

#define N_IMG 32
#define C_DIM 128
#define H_DIM 64
#define W_DIM 64
#define D_BOT 512
#define EPS_LN 1e-5f

#define M_TOT (N_IMG * H_DIM * W_DIM)      // 131072 spatial positions

// Scratch (device globals: allocation-free rule)
__device__ float g_y[(size_t)M_TOT * C_DIM];   // NHWC post-LN, 67 MB
__device__ float g_h[(size_t)M_TOT * D_BOT];   // hidden, 268 MB

// ---------------------------------------------------------------------------
// packed f32x2 helpers (sm_103a full-rate fp32 path)
// ---------------------------------------------------------------------------
__device__ __forceinline__ unsigned long long splat2(float x) {
    unsigned long long r;
    unsigned int xi = __float_as_uint(x);
    asm("mov.b64 %0, {%1, %1};" : "=l"(r) : "r"(xi));
    return r;
}
__device__ __forceinline__ void ffma2(unsigned long long& d,
                                      unsigned long long a,
                                      unsigned long long b) {
    asm("fma.rn.f32x2 %0, %1, %2, %0;" : "+l"(d) : "l"(a), "l"(b));
}
__device__ __forceinline__ float2 u2f(unsigned long long u) {
    float2 f;
    asm("mov.b64 {%0, %1}, %2;" : "=f"(f.x), "=f"(f.y) : "l"(u));
    return f;
}

// ---------------------------------------------------------------------------
// Kernel 1: depthwise 7x7 conv + bias + channel LayerNorm, NCHW -> NHWC
// One CTA per (n, h) row. 256 threads = 8 warps; warp handles 16 channels.
// ---------------------------------------------------------------------------
__global__ __launch_bounds__(256) void dwln_kernel(
    const float* __restrict__ x, const float* __restrict__ dw_w,
    const float* __restrict__ dw_b, const float* __restrict__ gamma,
    const float* __restrict__ beta)
{
    __shared__ float s_y[64 * 129];        // [w][c], stride 129 (conflict-free)
    __shared__ float s_buf[8][7][70];      // per-warp padded row windows

    const int bid = blockIdx.x;
    const int n = bid >> 6;
    const int h = bid & 63;
    const int tid = threadIdx.x;
    const int wg = tid >> 5;
    const int l  = tid & 31;

    for (int cc = 0; cc < 16; cc++) {
        const int c = wg * 16 + cc;
        // stage 7 input rows (64 wide + 3/3 zero halo)
        #pragma unroll
        for (int dy = 0; dy < 7; dy++) {
            const int hh = h + dy - 3;
            float v0 = 0.f, v1 = 0.f;
            if (hh >= 0 && hh < H_DIM) {
                const float* base = x + (((size_t)n * C_DIM + c) * H_DIM + hh) * W_DIM;
                v0 = base[l];
                v1 = base[l + 32];
            }
            s_buf[wg][dy][3 + l]  = v0;
            s_buf[wg][dy][35 + l] = v1;
            if (l < 3) { s_buf[wg][dy][l] = 0.f; s_buf[wg][dy][67 + l] = 0.f; }
        }
        __syncwarp();

        float acc0 = __ldg(&dw_b[c]);
        float acc1 = acc0;
        const float* wp = dw_w + c * 49;
        #pragma unroll
        for (int dy = 0; dy < 7; dy++) {
            #pragma unroll
            for (int dx = 0; dx < 7; dx++) {
                const float wv = __ldg(&wp[dy * 7 + dx]);
                acc0 += s_buf[wg][dy][l + dx] * wv;         // pos = 3 + (l + dx - 3)
                acc1 += s_buf[wg][dy][l + 32 + dx] * wv;
            }
        }
        s_y[l * 129 + c]        = acc0;
        s_y[(l + 32) * 129 + c] = acc1;
        __syncwarp();
    }
    __syncthreads();

    // LayerNorm over 128 channels. Warp wg handles w in [wg*8, wg*8+8)
    for (int wi = 0; wi < 8; wi++) {
        const int w = wg * 8 + wi;
        float v[4], s = 0.f, sq = 0.f;
        #pragma unroll
        for (int i = 0; i < 4; i++) {
            v[i] = s_y[w * 129 + l + 32 * i];
            s += v[i];
            sq += v[i] * v[i];
        }
        #pragma unroll
        for (int o = 16; o > 0; o >>= 1) {
            s  += __shfl_xor_sync(0xffffffffu, s, o);
            sq += __shfl_xor_sync(0xffffffffu, sq, o);
        }
        const float mu  = s * (1.f / 128.f);
        const float var = sq * (1.f / 128.f) - mu * mu;
        const float rs  = rsqrtf(var + EPS_LN);
        float* op = g_y + (((size_t)n * H_DIM + h) * W_DIM + w) * C_DIM;
        #pragma unroll
        for (int i = 0; i < 4; i++) {
            const int cix = l + 32 * i;
            op[cix] = (v[i] - mu) * rs * __ldg(&gamma[cix]) + __ldg(&beta[cix]);
        }
    }
}

// ---------------------------------------------------------------------------
// GEMM core: 128x128 CTA tile, K-chunks of 32, 256 threads, 8x8 microtile
// Shared layout: s[k][col] with stride 132 (16B-aligned, conflict-free LDS.128)
// ---------------------------------------------------------------------------
#define SM_STRIDE 132
#define SM_HALF   (32 * SM_STRIDE)   // 4224 floats per tile buffer

__device__ __forceinline__ void load_tile(const float* __restrict__ g, int row0,
                                          int ld, int k0, float* __restrict__ s,
                                          int tid)
{
    #pragma unroll
    for (int p = 0; p < 4; p++) {
        const int idx = p * 256 + tid;
        const int row = idx >> 3;          // 0..127
        const int k4  = (idx & 7) << 2;    // 0,4,...,28
        float4 v = *reinterpret_cast<const float4*>(
            g + (size_t)(row0 + row) * ld + k0 + k4);
        s[(k4 + 0) * SM_STRIDE + row] = v.x;
        s[(k4 + 1) * SM_STRIDE + row] = v.y;
        s[(k4 + 2) * SM_STRIDE + row] = v.z;
        s[(k4 + 3) * SM_STRIDE + row] = v.w;
    }
}

__device__ __forceinline__ void mma_tile(const float* __restrict__ sA,
                                         const float* __restrict__ sB,
                                         int tx, int ty,
                                         unsigned long long acc[8][4])
{
    #pragma unroll 8
    for (int k = 0; k < 32; k++) {
        const float4 a0 = *reinterpret_cast<const float4*>(sA + k * SM_STRIDE + 4 * ty);
        const float4 a1 = *reinterpret_cast<const float4*>(sA + k * SM_STRIDE + 4 * ty + 64);
        const ulonglong2 b0 = *reinterpret_cast<const ulonglong2*>(sB + k * SM_STRIDE + 4 * tx);
        const ulonglong2 b1 = *reinterpret_cast<const ulonglong2*>(sB + k * SM_STRIDE + 4 * tx + 64);
        unsigned long long as[8] = {splat2(a0.x), splat2(a0.y), splat2(a0.z), splat2(a0.w),
                                    splat2(a1.x), splat2(a1.y), splat2(a1.z), splat2(a1.w)};
        unsigned long long bs[4] = {b0.x, b0.y, b1.x, b1.y};
        #pragma unroll
        for (int r = 0; r < 8; r++)
            #pragma unroll
            for (int p = 0; p < 4; p++)
                ffma2(acc[r][p], as[r], bs[p]);
    }
}

// ---------------------------------------------------------------------------
// Kernel 2: h = relu(y @ W1^T + b1)   (M=131072, K=128, J=512)
// ---------------------------------------------------------------------------
__global__ __launch_bounds__(256, 2) void gemm1_kernel(
    const float* __restrict__ w1, const float* __restrict__ b1)
{
    __shared__ __align__(16) float smem[2 * SM_HALF];
    float* sA = smem;
    float* sB = smem + SM_HALF;

    const int tid = threadIdx.x;
    const int tx = tid & 15, ty = tid >> 4;
    const int j0 = blockIdx.x << 7;
    const int m0 = blockIdx.y << 7;

    unsigned long long acc[8][4];
    #pragma unroll
    for (int r = 0; r < 8; r++)
        #pragma unroll
        for (int p = 0; p < 4; p++) acc[r][p] = 0ULL;

    #pragma unroll 1
    for (int kc = 0; kc < 4; kc++) {
        load_tile(g_y, m0, C_DIM, kc * 32, sA, tid);
        load_tile(w1,  j0, C_DIM, kc * 32, sB, tid);
        __syncthreads();
        mma_tile(sA, sB, tx, ty, acc);
        __syncthreads();
    }

    const float4 bb0 = __ldg(reinterpret_cast<const float4*>(&b1[j0 + 4 * tx]));
    const float4 bb1 = __ldg(reinterpret_cast<const float4*>(&b1[j0 + 4 * tx + 64]));
    #pragma unroll
    for (int r = 0; r < 8; r++) {
        const int m = m0 + 4 * ty + (r & 3) + ((r >> 2) << 6);
        float* hp = g_h + (size_t)m * D_BOT + j0 + 4 * tx;
        float2 p0 = u2f(acc[r][0]), p1 = u2f(acc[r][1]);
        float4 v;
        v.x = fmaxf(p0.x + bb0.x, 0.f);
        v.y = fmaxf(p0.y + bb0.y, 0.f);
        v.z = fmaxf(p1.x + bb0.z, 0.f);
        v.w = fmaxf(p1.y + bb0.w, 0.f);
        *reinterpret_cast<float4*>(hp) = v;
        float2 p2 = u2f(acc[r][2]), p3 = u2f(acc[r][3]);
        v.x = fmaxf(p2.x + bb1.x, 0.f);
        v.y = fmaxf(p2.y + bb1.y, 0.f);
        v.z = fmaxf(p3.x + bb1.z, 0.f);
        v.w = fmaxf(p3.y + bb1.w, 0.f);
        *reinterpret_cast<float4*>(hp + 64) = v;
    }
}

// ---------------------------------------------------------------------------
// Kernel 3: out = x + (h @ W2^T + b2), written NCHW (M=131072, K=512, J=128)
// ---------------------------------------------------------------------------
__global__ __launch_bounds__(256, 2) void gemm2_kernel(
    const float* __restrict__ x, const float* __restrict__ w2,
    const float* __restrict__ b2, float* __restrict__ out)
{
    __shared__ __align__(16) float smem[2 * SM_HALF];
    float* sA = smem;
    float* sB = smem + SM_HALF;
    float* sC = smem;                       // reuse (64*132 = 8448 floats)

    const int tid = threadIdx.x;
    const int tx = tid & 15, ty = tid >> 4;
    const int m0 = blockIdx.y << 7;         // j0 = 0 (single 128-wide j tile)

    unsigned long long acc[8][4];
    #pragma unroll
    for (int r = 0; r < 8; r++)
        #pragma unroll
        for (int p = 0; p < 4; p++) acc[r][p] = 0ULL;

    #pragma unroll 1
    for (int kc = 0; kc < 16; kc++) {
        load_tile(g_h, m0, D_BOT, kc * 32, sA, tid);
        load_tile(w2,  0,  D_BOT, kc * 32, sB, tid);
        __syncthreads();
        mma_tile(sA, sB, tx, ty, acc);
        __syncthreads();
    }

    const int n = m0 >> 12;                 // 4096 positions per image
    #pragma unroll
    for (int hh = 0; hh < 2; hh++) {        // two 64-channel halves
        // stage results transposed: sC[j_in_half][m_local]
        #pragma unroll
        for (int r = 0; r < 8; r++) {
            const int mloc = 4 * ty + (r & 3) + ((r >> 2) << 6);
            #pragma unroll
            for (int p = 0; p < 2; p++) {
                const float2 f = u2f(acc[r][hh * 2 + p]);
                const int jr = 4 * tx + 2 * p;
                sC[jr * SM_STRIDE + mloc]       = f.x;
                sC[(jr + 1) * SM_STRIDE + mloc] = f.y;
            }
        }
        __syncthreads();
        // coalesced NCHW store with bias + residual
        #pragma unroll
        for (int q = 0; q < 8; q++) {
            const int idx = q * 256 + tid;
            const int j   = idx >> 5;          // 0..63
            const int m4  = (idx & 31) << 2;   // 0..124
            const int c   = hh * 64 + j;
            const size_t g = (((size_t)n * C_DIM + c) << 12) + (m0 & 4095) + m4;
            float4 v  = *reinterpret_cast<const float4*>(&sC[j * SM_STRIDE + m4]);
            float4 xr = *reinterpret_cast<const float4*>(&x[g]);
            const float bc = __ldg(&b2[c]);
            float4 o;
            o.x = v.x + xr.x + bc;
            o.y = v.y + xr.y + bc;
            o.z = v.z + xr.z + bc;
            o.w = v.w + xr.w + bc;
            *reinterpret_cast<float4*>(&out[g]) = o;
        }
        __syncthreads();
    }
}

// ---------------------------------------------------------------------------
extern "C" void kernel_launch(void* const* d_in, const int* in_sizes, int n_in,
                              void* d_out, int out_size)
{
    const float* x     = (const float*)d_in[0];
    const float* dw_w  = (const float*)d_in[1];
    const float* dw_b  = (const float*)d_in[2];
    const float* gamma = (const float*)d_in[3];
    const float* beta  = (const float*)d_in[4];
    const float* pw1_w = (const float*)d_in[5];
    const float* pw1_b = (const float*)d_in[6];
    const float* pw2_w = (const float*)d_in[7];
    const float* pw2_b = (const float*)d_in[8];
    float* out = (float*)d_out;

    dwln_kernel<<<N_IMG * H_DIM, 256>>>(x, dw_w, dw_b, gamma, beta);
    gemm1_kernel<<<dim3(D_BOT / 128, M_TOT / 128), 256>>>(pw1_w, pw1_b);
    gemm2_kernel<<<dim3(1, M_TOT / 128), 256>>>(x, pw2_w, pw2_b, out);
}

// round 3
// speedup vs baseline: 1.6149x; 1.6149x over previous
#include <cuda_runtime.h>
#include <cuda_bf16.h>
#include <cstdint>

// ConvNeXt block: dwconv7x7 -> LN -> 1x1 MLP via mma.sync bf16 (split hi/lo, K-concat) -> residual
#define N_IMG 32
#define C_DIM 128
#define H_DIM 64
#define W_DIM 64
#define D_BOT 512
#define EPS_LN 1e-5f
#define M_TOT (N_IMG * H_DIM * W_DIM)   // 131072

// ---------------- scratch (device globals; no allocs) ----------------------
__device__ __nv_bfloat16 g_yhi[(size_t)M_TOT * C_DIM];
__device__ __nv_bfloat16 g_ylo[(size_t)M_TOT * C_DIM];
__device__ __nv_bfloat16 g_hhi[(size_t)M_TOT * D_BOT];
__device__ __nv_bfloat16 g_hlo[(size_t)M_TOT * D_BOT];
__device__ __nv_bfloat16 g_w1hi[D_BOT * C_DIM];
__device__ __nv_bfloat16 g_w1lo[D_BOT * C_DIM];
__device__ __nv_bfloat16 g_w2hi[C_DIM * D_BOT];
__device__ __nv_bfloat16 g_w2lo[C_DIM * D_BOT];

// ---------------- helpers ---------------------------------------------------
__device__ __forceinline__ uint32_t s2u(const void* p) {
    uint32_t a;
    asm("{ .reg .u64 t; cvta.to.shared.u64 t, %1; cvt.u32.u64 %0, t; }"
        : "=r"(a) : "l"(p));
    return a;
}
__device__ __forceinline__ uint32_t lds32(uint32_t a) {
    uint32_t v;
    asm volatile("ld.shared.b32 %0, [%1];" : "=r"(v) : "r"(a));
    return v;
}
__device__ __forceinline__ void cpasync16(uint32_t dst, const void* src) {
    asm volatile("cp.async.cg.shared.global [%0], [%1], 16;" :: "r"(dst), "l"(src));
}
__device__ __forceinline__ void mma_bf16(float* c, uint32_t a0, uint32_t a1,
                                         uint32_t a2, uint32_t a3,
                                         uint32_t b0, uint32_t b1) {
    asm volatile(
        "mma.sync.aligned.m16n8k16.row.col.f32.bf16.bf16.f32 "
        "{%0,%1,%2,%3}, {%4,%5,%6,%7}, {%8,%9}, {%0,%1,%2,%3};"
        : "+f"(c[0]), "+f"(c[1]), "+f"(c[2]), "+f"(c[3])
        : "r"(a0), "r"(a1), "r"(a2), "r"(a3), "r"(b0), "r"(b1));
}
__device__ __forceinline__ uint32_t packb(__nv_bfloat16 a, __nv_bfloat16 b) {
    return (uint32_t)__bfloat16_as_ushort(a) |
           ((uint32_t)__bfloat16_as_ushort(b) << 16);
}
__device__ __forceinline__ void split_bf(float v, __nv_bfloat16& h, __nv_bfloat16& l) {
    h = __float2bfloat16(v);
    l = __float2bfloat16(v - __bfloat162float(h));
}

// ---------------------------------------------------------------------------
// Kernel 0: split weights to bf16 hi/lo
// ---------------------------------------------------------------------------
__global__ __launch_bounds__(256) void wconv_kernel(const float* __restrict__ w1,
                                                    const float* __restrict__ w2) {
    int i = blockIdx.x * 256 + threadIdx.x;
    if (i < D_BOT * C_DIM) {
        __nv_bfloat16 h, l;
        split_bf(w1[i], h, l);
        g_w1hi[i] = h; g_w1lo[i] = l;
        split_bf(w2[i], h, l);
        g_w2hi[i] = h; g_w2lo[i] = l;
    }
}

// ---------------------------------------------------------------------------
// Kernel 1: depthwise 7x7 conv + bias + channel LayerNorm -> bf16 hi/lo NHWC
// ---------------------------------------------------------------------------
__global__ __launch_bounds__(256) void dwln_kernel(
    const float* __restrict__ x, const float* __restrict__ dw_w,
    const float* __restrict__ dw_b, const float* __restrict__ gamma,
    const float* __restrict__ beta)
{
    __shared__ float s_y[64 * 129];
    __shared__ float s_buf[8][7][70];

    const int bid = blockIdx.x;
    const int n = bid >> 6;
    const int h = bid & 63;
    const int tid = threadIdx.x;
    const int wg = tid >> 5;
    const int l  = tid & 31;

    for (int cc = 0; cc < 16; cc++) {
        const int c = wg * 16 + cc;
        #pragma unroll
        for (int dy = 0; dy < 7; dy++) {
            const int hh = h + dy - 3;
            float v0 = 0.f, v1 = 0.f;
            if (hh >= 0 && hh < H_DIM) {
                const float* base = x + (((size_t)n * C_DIM + c) * H_DIM + hh) * W_DIM;
                v0 = base[l];
                v1 = base[l + 32];
            }
            s_buf[wg][dy][3 + l]  = v0;
            s_buf[wg][dy][35 + l] = v1;
            if (l < 3) { s_buf[wg][dy][l] = 0.f; s_buf[wg][dy][67 + l] = 0.f; }
        }
        __syncwarp();

        float acc0 = __ldg(&dw_b[c]);
        float acc1 = acc0;
        const float* wp = dw_w + c * 49;
        #pragma unroll
        for (int dy = 0; dy < 7; dy++)
            #pragma unroll
            for (int dx = 0; dx < 7; dx++) {
                const float wv = __ldg(&wp[dy * 7 + dx]);
                acc0 += s_buf[wg][dy][l + dx] * wv;
                acc1 += s_buf[wg][dy][l + 32 + dx] * wv;
            }
        s_y[l * 129 + c]        = acc0;
        s_y[(l + 32) * 129 + c] = acc1;
        __syncwarp();
    }
    __syncthreads();

    for (int wi = 0; wi < 8; wi++) {
        const int w = wg * 8 + wi;
        float v[4], s = 0.f, sq = 0.f;
        #pragma unroll
        for (int i = 0; i < 4; i++) {
            v[i] = s_y[w * 129 + l + 32 * i];
            s += v[i];
            sq += v[i] * v[i];
        }
        #pragma unroll
        for (int o = 16; o > 0; o >>= 1) {
            s  += __shfl_xor_sync(0xffffffffu, s, o);
            sq += __shfl_xor_sync(0xffffffffu, sq, o);
        }
        const float mu  = s * (1.f / 128.f);
        const float var = sq * (1.f / 128.f) - mu * mu;
        const float rs  = rsqrtf(var + EPS_LN);
        const size_t row = (((size_t)n * H_DIM + h) * W_DIM + w) * C_DIM;
        #pragma unroll
        for (int i = 0; i < 4; i++) {
            const int cix = l + 32 * i;
            const float val = (v[i] - mu) * rs * __ldg(&gamma[cix]) + __ldg(&beta[cix]);
            __nv_bfloat16 hi, lo;
            split_bf(val, hi, lo);
            g_yhi[row + cix] = hi;
            g_ylo[row + cix] = lo;
        }
    }
}

// ---------------------------------------------------------------------------
// mma.sync GEMM core: CTA 128x128, 8 warps (2x4), warp tile 64x32
// smem: A,B tiles 128 rows x 64 bf16, row stride 144B; double buffered.
// ---------------------------------------------------------------------------
#define ROW_B   144              // padded row stride in bytes (72 bf16)
#define MAT_B   (128 * ROW_B)    // 18432 bytes per matrix
#define BUF_B   (2 * MAT_B)      // 36864 bytes per stage buffer
#define SMEM_DYN (2 * BUF_B)     // 73728

__device__ __forceinline__ void stage(const __nv_bfloat16* __restrict__ A,
                                      const __nv_bfloat16* __restrict__ B,
                                      int lda, int ldb, int arow0, int brow0,
                                      int kk, uint32_t sbuf) {
    const int t = threadIdx.x;
    #pragma unroll
    for (int p = 0; p < 4; p++) {
        const int idx = p * 256 + t;
        const int row = idx >> 3, seg = idx & 7;
        cpasync16(sbuf + row * ROW_B + seg * 16,
                  A + (size_t)(arow0 + row) * lda + kk + seg * 8);
    }
    #pragma unroll
    for (int p = 0; p < 4; p++) {
        const int idx = p * 256 + t;
        const int row = idx >> 3, seg = idx & 7;
        cpasync16(sbuf + MAT_B + row * ROW_B + seg * 16,
                  B + (size_t)(brow0 + row) * ldb + kk + seg * 8);
    }
}

__device__ __forceinline__ void compute_chunk(uint32_t sA, uint32_t sB,
                                              int wm, int wn, int r, int q,
                                              float c[4][4][4]) {
    #pragma unroll
    for (int ks = 0; ks < 4; ks++) {
        const uint32_t koff = (ks * 16 + 2 * q) * 2;
        uint32_t b0[4], b1[4];
        #pragma unroll
        for (int nf = 0; nf < 4; nf++) {
            const uint32_t ad = sB + (wn * 32 + nf * 8 + r) * ROW_B + koff;
            b0[nf] = lds32(ad);
            b1[nf] = lds32(ad + 16);
        }
        #pragma unroll
        for (int mf = 0; mf < 4; mf++) {
            const uint32_t ad = sA + (wm * 64 + mf * 16 + r) * ROW_B + koff;
            const uint32_t a0 = lds32(ad);
            const uint32_t a1 = lds32(ad + 8 * ROW_B);
            const uint32_t a2 = lds32(ad + 16);
            const uint32_t a3 = lds32(ad + 8 * ROW_B + 16);
            #pragma unroll
            for (int nf = 0; nf < 4; nf++)
                mma_bf16(c[mf][nf], a0, a1, a2, a3, b0[nf], b1[nf]);
        }
    }
}

template <int NC, int KPT>
__device__ __forceinline__ void run_gemm(
    const __nv_bfloat16* A0, const __nv_bfloat16* A1, const __nv_bfloat16* A2,
    const __nv_bfloat16* B0, const __nv_bfloat16* B1, const __nv_bfloat16* B2,
    int lda, int ldb, int arow0, int brow0, uint32_t sbase, float c[4][4][4])
{
    const int tid = threadIdx.x;
    const int wid = tid >> 5, lane = tid & 31;
    const int wm = wid >> 2, wn = wid & 3;
    const int r = lane >> 2, q = lane & 3;

    const __nv_bfloat16* As[3] = {A0, A1, A2};
    const __nv_bfloat16* Bs[3] = {B0, B1, B2};

    stage(As[0], Bs[0], lda, ldb, arow0, brow0, 0, sbase);
    asm volatile("cp.async.commit_group;");

    #pragma unroll 1
    for (int i = 0; i < NC; i++) {
        if (i + 1 < NC) {
            const int t2 = (i + 1) / KPT;
            const int kk = ((i + 1) % KPT) * 64;
            stage(As[t2], Bs[t2], lda, ldb, arow0, brow0, kk,
                  sbase + ((i + 1) & 1) * BUF_B);
            asm volatile("cp.async.commit_group;");
            asm volatile("cp.async.wait_group 1;");
        } else {
            asm volatile("cp.async.wait_group 0;");
        }
        __syncthreads();
        const uint32_t sb = sbase + (i & 1) * BUF_B;
        compute_chunk(sb, sb + MAT_B, wm, wn, r, q, c);
        __syncthreads();
    }
}

// ---------------------------------------------------------------------------
// Kernel 2: h = relu(y @ W1^T + b1) -> bf16 hi/lo   (K_eff = 384)
// ---------------------------------------------------------------------------
__global__ __launch_bounds__(256, 2) void gemm1_mma(const float* __restrict__ bias1)
{
    extern __shared__ char dsm[];
    float c[4][4][4];
    #pragma unroll
    for (int a = 0; a < 4; a++)
        #pragma unroll
        for (int b = 0; b < 4; b++)
            #pragma unroll
            for (int d = 0; d < 4; d++) c[a][b][d] = 0.f;

    const int j0 = blockIdx.x << 7;
    const int m0 = blockIdx.y << 7;

    run_gemm<6, 2>(g_yhi, g_ylo, g_yhi, g_w1hi, g_w1hi, g_w1lo,
                   C_DIM, C_DIM, m0, j0, s2u(dsm), c);

    const int tid = threadIdx.x;
    const int wid = tid >> 5, lane = tid & 31;
    const int wm = wid >> 2, wn = wid & 3;
    const int r = lane >> 2, q = lane & 3;

    uint32_t* dh = (uint32_t*)g_hhi;
    uint32_t* dl = (uint32_t*)g_hlo;
    #pragma unroll
    for (int nf = 0; nf < 4; nf++) {
        const int jc = j0 + wn * 32 + nf * 8 + 2 * q;
        const float2 bb = *reinterpret_cast<const float2*>(bias1 + jc);
        #pragma unroll
        for (int mf = 0; mf < 4; mf++)
            #pragma unroll
            for (int hf = 0; hf < 2; hf++) {
                const int row = m0 + wm * 64 + mf * 16 + r + 8 * hf;
                const float v0 = fmaxf(c[mf][nf][2 * hf]     + bb.x, 0.f);
                const float v1 = fmaxf(c[mf][nf][2 * hf + 1] + bb.y, 0.f);
                __nv_bfloat16 h0, l0, h1, l1;
                split_bf(v0, h0, l0);
                split_bf(v1, h1, l1);
                const size_t idx = (size_t)row * (D_BOT / 2) + (jc >> 1);
                dh[idx] = packb(h0, h1);
                dl[idx] = packb(l0, l1);
            }
    }
}

// ---------------------------------------------------------------------------
// Kernel 3: out = x + (h @ W2^T + b2), NCHW + residual   (K_eff = 1536)
// ---------------------------------------------------------------------------
__global__ __launch_bounds__(256, 2) void gemm2_mma(const float* __restrict__ x,
                                                    const float* __restrict__ b2,
                                                    float* __restrict__ out)
{
    extern __shared__ char dsm[];
    float c[4][4][4];
    #pragma unroll
    for (int a = 0; a < 4; a++)
        #pragma unroll
        for (int b = 0; b < 4; b++)
            #pragma unroll
            for (int d = 0; d < 4; d++) c[a][b][d] = 0.f;

    const int m0 = blockIdx.x << 7;

    run_gemm<24, 8>(g_hhi, g_hlo, g_hhi, g_w2hi, g_w2hi, g_w2lo,
                    D_BOT, D_BOT, m0, 0, s2u(dsm), c);

    const int tid = threadIdx.x;
    const int wid = tid >> 5, lane = tid & 31;
    const int wm = wid >> 2, wn = wid & 3;
    const int r = lane >> 2, q = lane & 3;

    float* sC = (float*)dsm;                  // 64 x 132 floats per half
    const int n  = m0 >> 12;
    const int sp0 = m0 & 4095;

    #pragma unroll 1
    for (int hh = 0; hh < 2; hh++) {
        if ((wn >> 1) == hh) {
            #pragma unroll
            for (int nf = 0; nf < 4; nf++) {
                const int cl = (wn & 1) * 32 + nf * 8 + 2 * q;
                #pragma unroll
                for (int mf = 0; mf < 4; mf++)
                    #pragma unroll
                    for (int hf = 0; hf < 2; hf++) {
                        const int ml = wm * 64 + mf * 16 + r + 8 * hf;
                        sC[cl * 132 + ml]       = c[mf][nf][2 * hf];
                        sC[(cl + 1) * 132 + ml] = c[mf][nf][2 * hf + 1];
                    }
            }
        }
        __syncthreads();
        #pragma unroll
        for (int qi = 0; qi < 8; qi++) {
            const int idx = qi * 256 + tid;
            const int j   = idx >> 5;
            const int m4  = (idx & 31) << 2;
            const int ch  = hh * 64 + j;
            const float bc = __ldg(&b2[ch]);
            const size_t g = ((size_t)(n * C_DIM + ch) << 12) + sp0 + m4;
            float4 v  = *reinterpret_cast<const float4*>(&sC[j * 132 + m4]);
            float4 xv = *reinterpret_cast<const float4*>(x + g);
            float4 o;
            o.x = v.x + xv.x + bc;
            o.y = v.y + xv.y + bc;
            o.z = v.z + xv.z + bc;
            o.w = v.w + xv.w + bc;
            *reinterpret_cast<float4*>(out + g) = o;
        }
        __syncthreads();
    }
}

// ---------------------------------------------------------------------------
extern "C" void kernel_launch(void* const* d_in, const int* in_sizes, int n_in,
                              void* d_out, int out_size)
{
    const float* x     = (const float*)d_in[0];
    const float* dw_w  = (const float*)d_in[1];
    const float* dw_b  = (const float*)d_in[2];
    const float* gamma = (const float*)d_in[3];
    const float* beta  = (const float*)d_in[4];
    const float* pw1_w = (const float*)d_in[5];
    const float* pw1_b = (const float*)d_in[6];
    const float* pw2_w = (const float*)d_in[7];
    const float* pw2_b = (const float*)d_in[8];
    float* out = (float*)d_out;

    static bool attr_done = false;
    if (!attr_done) {
        cudaFuncSetAttribute(gemm1_mma, cudaFuncAttributeMaxDynamicSharedMemorySize, SMEM_DYN);
        cudaFuncSetAttribute(gemm2_mma, cudaFuncAttributeMaxDynamicSharedMemorySize, SMEM_DYN);
        attr_done = true;
    }

    wconv_kernel<<<(D_BOT * C_DIM + 255) / 256, 256>>>(pw1_w, pw2_w);
    dwln_kernel<<<N_IMG * H_DIM, 256>>>(x, dw_w, dw_b, gamma, beta);
    gemm1_mma<<<dim3(D_BOT / 128, M_TOT / 128), 256, SMEM_DYN>>>(pw1_b);
    gemm2_mma<<<M_TOT / 128, 256, SMEM_DYN>>>(x, pw2_b, out);
}

// round 4
// speedup vs baseline: 1.7877x; 1.1070x over previous
#include <cuda_runtime.h>
#include <cuda_bf16.h>
#include <cstdint>

// ConvNeXt block: dwconv7x7 -> LN -> 1x1 MLP via mma.sync bf16 (split hi/lo) -> residual
#define N_IMG 32
#define C_DIM 128
#define H_DIM 64
#define W_DIM 64
#define D_BOT 512
#define EPS_LN 1e-5f
#define M_TOT (N_IMG * H_DIM * W_DIM)   // 131072

// ---------------- scratch (device globals; no allocs) ----------------------
__device__ __nv_bfloat16 g_yhi[(size_t)M_TOT * C_DIM];
__device__ __nv_bfloat16 g_ylo[(size_t)M_TOT * C_DIM];
__device__ __nv_bfloat16 g_hhi[(size_t)M_TOT * D_BOT];
__device__ __nv_bfloat16 g_hlo[(size_t)M_TOT * D_BOT];
__device__ __nv_bfloat16 g_w1hi[D_BOT * C_DIM];
__device__ __nv_bfloat16 g_w1lo[D_BOT * C_DIM];
__device__ __nv_bfloat16 g_w2hi[C_DIM * D_BOT];
__device__ __nv_bfloat16 g_w2lo[C_DIM * D_BOT];

// ---------------- helpers ---------------------------------------------------
__device__ __forceinline__ uint32_t s2u(const void* p) {
    uint32_t a;
    asm("{ .reg .u64 t; cvta.to.shared.u64 t, %1; cvt.u32.u64 %0, t; }"
        : "=r"(a) : "l"(p));
    return a;
}
__device__ __forceinline__ void cpasync16(uint32_t dst, const void* src) {
    asm volatile("cp.async.cg.shared.global [%0], [%1], 16;" :: "r"(dst), "l"(src));
}
__device__ __forceinline__ void ldsm4(uint32_t* r, uint32_t addr) {
    asm volatile("ldmatrix.sync.aligned.m8n8.x4.shared.b16 {%0,%1,%2,%3}, [%4];"
                 : "=r"(r[0]), "=r"(r[1]), "=r"(r[2]), "=r"(r[3]) : "r"(addr));
}
__device__ __forceinline__ void mma_bf16(float* c, uint32_t a0, uint32_t a1,
                                         uint32_t a2, uint32_t a3,
                                         uint32_t b0, uint32_t b1) {
    asm volatile(
        "mma.sync.aligned.m16n8k16.row.col.f32.bf16.bf16.f32 "
        "{%0,%1,%2,%3}, {%4,%5,%6,%7}, {%8,%9}, {%0,%1,%2,%3};"
        : "+f"(c[0]), "+f"(c[1]), "+f"(c[2]), "+f"(c[3])
        : "r"(a0), "r"(a1), "r"(a2), "r"(a3), "r"(b0), "r"(b1));
}
__device__ __forceinline__ uint32_t packb(__nv_bfloat16 a, __nv_bfloat16 b) {
    return (uint32_t)__bfloat16_as_ushort(a) |
           ((uint32_t)__bfloat16_as_ushort(b) << 16);
}
__device__ __forceinline__ void split_bf(float v, __nv_bfloat16& h, __nv_bfloat16& l) {
    h = __float2bfloat16(v);
    l = __float2bfloat16(v - __bfloat162float(h));
}

// ---------------------------------------------------------------------------
// Kernel 0: split weights to bf16 hi/lo
// ---------------------------------------------------------------------------
__global__ __launch_bounds__(256) void wconv_kernel(const float* __restrict__ w1,
                                                    const float* __restrict__ w2) {
    int i = blockIdx.x * 256 + threadIdx.x;
    if (i < D_BOT * C_DIM) {
        __nv_bfloat16 h, l;
        split_bf(w1[i], h, l);
        g_w1hi[i] = h; g_w1lo[i] = l;
        split_bf(w2[i], h, l);
        g_w2hi[i] = h; g_w2lo[i] = l;
    }
}

// ---------------------------------------------------------------------------
// Kernel 1: dwconv 7x7 + bias + LN -> bf16 hi/lo NHWC. Sliding-window regs.
// CTA = (n,h) row, 256 threads. Warp: 2 channels at a time (half-warp each);
// lane computes 4 consecutive w outputs from a 10-float register window.
// ---------------------------------------------------------------------------
#define DWLN_SBUF (8 * 2 * 7 * 72)          // floats
#define DWLN_SY   (64 * 129)
#define DWLN_SMEM ((DWLN_SBUF + DWLN_SY) * 4)

__global__ __launch_bounds__(256) void dwln_kernel(
    const float* __restrict__ x, const float* __restrict__ dw_w,
    const float* __restrict__ dw_b, const float* __restrict__ gamma,
    const float* __restrict__ beta)
{
    extern __shared__ float dyn[];
    float* s_buf = dyn;                 // [8 warps][2 ch][7 rows][72]
    float* s_y   = dyn + DWLN_SBUF;     // [64 w][129]

    const int bid = blockIdx.x;
    const int n = bid >> 6;
    const int h = bid & 63;
    const int tid = threadIdx.x;
    const int wg = tid >> 5;
    const int l  = tid & 31;
    const int half = l >> 4;
    const int li = l & 15;

    #pragma unroll 1
    for (int it = 0; it < 8; it++) {
        const int c = wg * 16 + it * 2 + half;
        float* rowbuf = s_buf + (size_t)(wg * 2 + half) * 7 * 72;
        // stage 7 padded rows for this channel (halo zeros)
        #pragma unroll
        for (int dy = 0; dy < 7; dy++) {
            const int hh = h + dy - 3;
            float4 v = make_float4(0.f, 0.f, 0.f, 0.f);
            if (hh >= 0 && hh < H_DIM)
                v = *reinterpret_cast<const float4*>(
                    x + (((size_t)n * C_DIM + c) * H_DIM + hh) * W_DIM + 4 * li);
            float* rb = rowbuf + dy * 72;
            rb[3 + 4 * li] = v.x;
            rb[4 + 4 * li] = v.y;
            rb[5 + 4 * li] = v.z;
            rb[6 + 4 * li] = v.w;
            if (li == 0)  { rb[0] = 0.f; rb[1] = 0.f; rb[2] = 0.f; }
            if (li == 15) { rb[67] = 0.f; rb[68] = 0.f; rb[69] = 0.f; }
        }
        __syncwarp();

        const float bias = __ldg(&dw_b[c]);
        float acc[4] = {bias, bias, bias, bias};
        const float* wp = dw_w + c * 49;
        #pragma unroll
        for (int dy = 0; dy < 7; dy++) {
            const float* rb = rowbuf + dy * 72 + 4 * li;
            const float4 A = *reinterpret_cast<const float4*>(rb);
            const float4 B = *reinterpret_cast<const float4*>(rb + 4);
            const float2 Cc = *reinterpret_cast<const float2*>(rb + 8);
            const float v[10] = {A.x, A.y, A.z, A.w, B.x, B.y, B.z, B.w, Cc.x, Cc.y};
            #pragma unroll
            for (int dx = 0; dx < 7; dx++) {
                const float wv = __ldg(&wp[dy * 7 + dx]);
                acc[0] += v[dx]     * wv;
                acc[1] += v[dx + 1] * wv;
                acc[2] += v[dx + 2] * wv;
                acc[3] += v[dx + 3] * wv;
            }
        }
        #pragma unroll
        for (int j = 0; j < 4; j++)
            s_y[(4 * li + j) * 129 + c] = acc[j];
        __syncwarp();
    }
    __syncthreads();

    // LayerNorm over 128 channels; warp wg handles w in [wg*8, wg*8+8)
    for (int wi = 0; wi < 8; wi++) {
        const int w = wg * 8 + wi;
        float v[4], s = 0.f, sq = 0.f;
        #pragma unroll
        for (int i = 0; i < 4; i++) {
            v[i] = s_y[w * 129 + l + 32 * i];
            s += v[i];
            sq += v[i] * v[i];
        }
        #pragma unroll
        for (int o = 16; o > 0; o >>= 1) {
            s  += __shfl_xor_sync(0xffffffffu, s, o);
            sq += __shfl_xor_sync(0xffffffffu, sq, o);
        }
        const float mu  = s * (1.f / 128.f);
        const float var = sq * (1.f / 128.f) - mu * mu;
        const float rs  = rsqrtf(var + EPS_LN);
        const size_t row = (((size_t)n * H_DIM + h) * W_DIM + w) * C_DIM;
        #pragma unroll
        for (int i = 0; i < 4; i++) {
            const int cix = l + 32 * i;
            const float val = (v[i] - mu) * rs * __ldg(&gamma[cix]) + __ldg(&beta[cix]);
            __nv_bfloat16 hi, lo;
            split_bf(val, hi, lo);
            g_yhi[row + cix] = hi;
            g_ylo[row + cix] = lo;
        }
    }
}

// ---------------------------------------------------------------------------
// mma.sync GEMM core with ldmatrix + stage-once/3-pass hi-lo terms.
// CTA 128x128, 8 warps (2x4), warp tile 64x32. K-chunk 32.
// smem per buffer: 4 matrices (Ahi,Alo,Bhi,Blo), each 128 rows x 80B. Dbl-buf.
// ---------------------------------------------------------------------------
#define ROW2   80
#define MAT2   (128 * ROW2)      // 10240 B
#define BUF2   (4 * MAT2)        // 40960 B
#define SMEM_G (2 * BUF2)        // 81920 B

__device__ __forceinline__ void stage4(
    const __nv_bfloat16* __restrict__ Ah, const __nv_bfloat16* __restrict__ Al,
    const __nv_bfloat16* __restrict__ Bh, const __nv_bfloat16* __restrict__ Bl,
    int lda, int ldb, int arow0, int brow0, int k0, uint32_t buf)
{
    const int t = threadIdx.x;
    #pragma unroll
    for (int p = 0; p < 2; p++) {
        const int idx = p * 256 + t;          // 0..511
        const int row = idx >> 2, seg = idx & 3;
        const int koff = k0 + seg * 8;
        const uint32_t d = buf + row * ROW2 + seg * 16;
        cpasync16(d,            Ah + (size_t)(arow0 + row) * lda + koff);
        cpasync16(d + MAT2,     Al + (size_t)(arow0 + row) * lda + koff);
        cpasync16(d + 2 * MAT2, Bh + (size_t)(brow0 + row) * ldb + koff);
        cpasync16(d + 3 * MAT2, Bl + (size_t)(brow0 + row) * ldb + koff);
    }
}

__device__ __forceinline__ void chunk3(uint32_t buf, int wm, int wn, int lane,
                                       float c[4][4][4])
{
    #pragma unroll
    for (int ks = 0; ks < 2; ks++) {
        const uint32_t aAddr = buf + (wm * 64 + (lane & 15)) * ROW2 +
                               ks * 32 + (lane >> 4) * 16;
        const uint32_t bAddr = buf + 2 * MAT2 +
                               (wn * 32 + (lane & 7) + (lane >> 4) * 8) * ROW2 +
                               ks * 32 + ((lane >> 3) & 1) * 16;
        uint32_t Af[4][4], Bh[2][4], Bl[2][4];
        #pragma unroll
        for (int mf = 0; mf < 4; mf++) ldsm4(Af[mf], aAddr + mf * (16 * ROW2));
        #pragma unroll
        for (int n2 = 0; n2 < 2; n2++) ldsm4(Bh[n2], bAddr + n2 * (16 * ROW2));
        // term0: Ahi * Bhi
        #pragma unroll
        for (int mf = 0; mf < 4; mf++)
            #pragma unroll
            for (int nf = 0; nf < 4; nf++)
                mma_bf16(c[mf][nf], Af[mf][0], Af[mf][1], Af[mf][2], Af[mf][3],
                         Bh[nf >> 1][(nf & 1) * 2], Bh[nf >> 1][(nf & 1) * 2 + 1]);
        // term1: Ahi * Blo
        #pragma unroll
        for (int n2 = 0; n2 < 2; n2++) ldsm4(Bl[n2], bAddr + MAT2 + n2 * (16 * ROW2));
        #pragma unroll
        for (int mf = 0; mf < 4; mf++)
            #pragma unroll
            for (int nf = 0; nf < 4; nf++)
                mma_bf16(c[mf][nf], Af[mf][0], Af[mf][1], Af[mf][2], Af[mf][3],
                         Bl[nf >> 1][(nf & 1) * 2], Bl[nf >> 1][(nf & 1) * 2 + 1]);
        // term2: Alo * Bhi  (overwrite A frags)
        #pragma unroll
        for (int mf = 0; mf < 4; mf++) ldsm4(Af[mf], aAddr + MAT2 + mf * (16 * ROW2));
        #pragma unroll
        for (int mf = 0; mf < 4; mf++)
            #pragma unroll
            for (int nf = 0; nf < 4; nf++)
                mma_bf16(c[mf][nf], Af[mf][0], Af[mf][1], Af[mf][2], Af[mf][3],
                         Bh[nf >> 1][(nf & 1) * 2], Bh[nf >> 1][(nf & 1) * 2 + 1]);
    }
}

template <int NC>
__device__ __forceinline__ void run_gemm(
    const __nv_bfloat16* Ah, const __nv_bfloat16* Al,
    const __nv_bfloat16* Bh, const __nv_bfloat16* Bl,
    int lda, int ldb, int arow0, int brow0, uint32_t sbase, float c[4][4][4])
{
    const int tid = threadIdx.x;
    const int wid = tid >> 5, lane = tid & 31;
    const int wm = wid >> 2, wn = wid & 3;

    stage4(Ah, Al, Bh, Bl, lda, ldb, arow0, brow0, 0, sbase);
    asm volatile("cp.async.commit_group;");

    #pragma unroll 1
    for (int i = 0; i < NC; i++) {
        if (i + 1 < NC) {
            stage4(Ah, Al, Bh, Bl, lda, ldb, arow0, brow0, (i + 1) * 32,
                   sbase + ((i + 1) & 1) * BUF2);
            asm volatile("cp.async.commit_group;");
            asm volatile("cp.async.wait_group 1;");
        } else {
            asm volatile("cp.async.wait_group 0;");
        }
        __syncthreads();
        chunk3(sbase + (i & 1) * BUF2, wm, wn, lane, c);
        __syncthreads();
    }
}

// ---------------------------------------------------------------------------
// Kernel 2: h = relu(y @ W1^T + b1) -> bf16 hi/lo
// ---------------------------------------------------------------------------
__global__ __launch_bounds__(256, 2) void gemm1_mma(const float* __restrict__ bias1)
{
    extern __shared__ char dsm[];
    float c[4][4][4];
    #pragma unroll
    for (int a = 0; a < 4; a++)
        #pragma unroll
        for (int b = 0; b < 4; b++)
            #pragma unroll
            for (int d = 0; d < 4; d++) c[a][b][d] = 0.f;

    const int j0 = blockIdx.x << 7;
    const int m0 = blockIdx.y << 7;

    run_gemm<4>(g_yhi, g_ylo, g_w1hi, g_w1lo, C_DIM, C_DIM, m0, j0, s2u(dsm), c);

    const int tid = threadIdx.x;
    const int wid = tid >> 5, lane = tid & 31;
    const int wm = wid >> 2, wn = wid & 3;
    const int r = lane >> 2, q = lane & 3;

    uint32_t* dh = (uint32_t*)g_hhi;
    uint32_t* dl = (uint32_t*)g_hlo;
    #pragma unroll
    for (int nf = 0; nf < 4; nf++) {
        const int jc = j0 + wn * 32 + nf * 8 + 2 * q;
        const float2 bb = *reinterpret_cast<const float2*>(bias1 + jc);
        #pragma unroll
        for (int mf = 0; mf < 4; mf++)
            #pragma unroll
            for (int hf = 0; hf < 2; hf++) {
                const int row = m0 + wm * 64 + mf * 16 + r + 8 * hf;
                const float v0 = fmaxf(c[mf][nf][2 * hf]     + bb.x, 0.f);
                const float v1 = fmaxf(c[mf][nf][2 * hf + 1] + bb.y, 0.f);
                __nv_bfloat16 h0, l0, h1, l1;
                split_bf(v0, h0, l0);
                split_bf(v1, h1, l1);
                const size_t idx = (size_t)row * (D_BOT / 2) + (jc >> 1);
                dh[idx] = packb(h0, h1);
                dl[idx] = packb(l0, l1);
            }
    }
}

// ---------------------------------------------------------------------------
// Kernel 3: out = x + (h @ W2^T + b2), NCHW + residual
// ---------------------------------------------------------------------------
__global__ __launch_bounds__(256, 2) void gemm2_mma(const float* __restrict__ x,
                                                    const float* __restrict__ b2,
                                                    float* __restrict__ out)
{
    extern __shared__ char dsm[];
    float c[4][4][4];
    #pragma unroll
    for (int a = 0; a < 4; a++)
        #pragma unroll
        for (int b = 0; b < 4; b++)
            #pragma unroll
            for (int d = 0; d < 4; d++) c[a][b][d] = 0.f;

    const int m0 = blockIdx.x << 7;

    run_gemm<16>(g_hhi, g_hlo, g_w2hi, g_w2lo, D_BOT, D_BOT, m0, 0, s2u(dsm), c);

    const int tid = threadIdx.x;
    const int wid = tid >> 5, lane = tid & 31;
    const int wm = wid >> 2, wn = wid & 3;
    const int r = lane >> 2, q = lane & 3;

    float* sC = (float*)dsm;                  // 64 x 132 floats per half
    const int n  = m0 >> 12;
    const int sp0 = m0 & 4095;

    #pragma unroll 1
    for (int hh = 0; hh < 2; hh++) {
        if ((wn >> 1) == hh) {
            #pragma unroll
            for (int nf = 0; nf < 4; nf++) {
                const int cl = (wn & 1) * 32 + nf * 8 + 2 * q;
                #pragma unroll
                for (int mf = 0; mf < 4; mf++)
                    #pragma unroll
                    for (int hf = 0; hf < 2; hf++) {
                        const int ml = wm * 64 + mf * 16 + r + 8 * hf;
                        sC[cl * 132 + ml]       = c[mf][nf][2 * hf];
                        sC[(cl + 1) * 132 + ml] = c[mf][nf][2 * hf + 1];
                    }
            }
        }
        __syncthreads();
        #pragma unroll
        for (int qi = 0; qi < 8; qi++) {
            const int idx = qi * 256 + tid;
            const int j   = idx >> 5;
            const int m4  = (idx & 31) << 2;
            const int ch  = hh * 64 + j;
            const float bc = __ldg(&b2[ch]);
            const size_t g = ((size_t)(n * C_DIM + ch) << 12) + sp0 + m4;
            float4 v  = *reinterpret_cast<const float4*>(&sC[j * 132 + m4]);
            float4 xv = *reinterpret_cast<const float4*>(x + g);
            float4 o;
            o.x = v.x + xv.x + bc;
            o.y = v.y + xv.y + bc;
            o.z = v.z + xv.z + bc;
            o.w = v.w + xv.w + bc;
            *reinterpret_cast<float4*>(out + g) = o;
        }
        __syncthreads();
    }
}

// ---------------------------------------------------------------------------
extern "C" void kernel_launch(void* const* d_in, const int* in_sizes, int n_in,
                              void* d_out, int out_size)
{
    const float* x     = (const float*)d_in[0];
    const float* dw_w  = (const float*)d_in[1];
    const float* dw_b  = (const float*)d_in[2];
    const float* gamma = (const float*)d_in[3];
    const float* beta  = (const float*)d_in[4];
    const float* pw1_w = (const float*)d_in[5];
    const float* pw1_b = (const float*)d_in[6];
    const float* pw2_w = (const float*)d_in[7];
    const float* pw2_b = (const float*)d_in[8];
    float* out = (float*)d_out;

    static bool attr_done = false;
    if (!attr_done) {
        cudaFuncSetAttribute(dwln_kernel, cudaFuncAttributeMaxDynamicSharedMemorySize, DWLN_SMEM);
        cudaFuncSetAttribute(gemm1_mma, cudaFuncAttributeMaxDynamicSharedMemorySize, SMEM_G);
        cudaFuncSetAttribute(gemm2_mma, cudaFuncAttributeMaxDynamicSharedMemorySize, SMEM_G);
        attr_done = true;
    }

    wconv_kernel<<<(D_BOT * C_DIM + 255) / 256, 256>>>(pw1_w, pw2_w);
    dwln_kernel<<<N_IMG * H_DIM, 256, DWLN_SMEM>>>(x, dw_w, dw_b, gamma, beta);
    gemm1_mma<<<dim3(D_BOT / 128, M_TOT / 128), 256, SMEM_G>>>(pw1_b);
    gemm2_mma<<<M_TOT / 128, 256, SMEM_G>>>(x, pw2_b, out);
}

// round 5
// speedup vs baseline: 2.3509x; 1.3151x over previous
#include <cuda_runtime.h>
#include <cuda_fp16.h>
#include <cstdint>

// ConvNeXt block: dwconv7x7 -> LN -> 1x1 MLP via mma.sync fp16 (act single, wt hi/lo) -> residual
#define N_IMG 32
#define C_DIM 128
#define H_DIM 64
#define W_DIM 64
#define D_BOT 512
#define EPS_LN 1e-5f
#define M_TOT (N_IMG * H_DIM * W_DIM)   // 131072

// ---------------- scratch (device globals; no allocs) ----------------------
__device__ __half g_y[(size_t)M_TOT * C_DIM];
__device__ __half g_h[(size_t)M_TOT * D_BOT];
__device__ __half g_w1hi[D_BOT * C_DIM];
__device__ __half g_w1lo[D_BOT * C_DIM];
__device__ __half g_w2hi[C_DIM * D_BOT];
__device__ __half g_w2lo[C_DIM * D_BOT];

// ---------------- helpers ---------------------------------------------------
__device__ __forceinline__ uint32_t s2u(const void* p) {
    uint32_t a;
    asm("{ .reg .u64 t; cvta.to.shared.u64 t, %1; cvt.u32.u64 %0, t; }"
        : "=r"(a) : "l"(p));
    return a;
}
__device__ __forceinline__ void cpasync16(uint32_t dst, const void* src) {
    asm volatile("cp.async.cg.shared.global [%0], [%1], 16;" :: "r"(dst), "l"(src));
}
__device__ __forceinline__ void ldsm4(uint32_t* r, uint32_t addr) {
    asm volatile("ldmatrix.sync.aligned.m8n8.x4.shared.b16 {%0,%1,%2,%3}, [%4];"
                 : "=r"(r[0]), "=r"(r[1]), "=r"(r[2]), "=r"(r[3]) : "r"(addr));
}
__device__ __forceinline__ void mma_f16(float* c, uint32_t a0, uint32_t a1,
                                        uint32_t a2, uint32_t a3,
                                        uint32_t b0, uint32_t b1) {
    asm volatile(
        "mma.sync.aligned.m16n8k16.row.col.f32.f16.f16.f32 "
        "{%0,%1,%2,%3}, {%4,%5,%6,%7}, {%8,%9}, {%0,%1,%2,%3};"
        : "+f"(c[0]), "+f"(c[1]), "+f"(c[2]), "+f"(c[3])
        : "r"(a0), "r"(a1), "r"(a2), "r"(a3), "r"(b0), "r"(b1));
}
__device__ __forceinline__ uint32_t packh(__half a, __half b) {
    return (uint32_t)__half_as_ushort(a) | ((uint32_t)__half_as_ushort(b) << 16);
}
__device__ __forceinline__ void split_h(float v, __half& h, __half& l) {
    h = __float2half(v);
    l = __float2half(v - __half2float(h));
}

// ---------------------------------------------------------------------------
// Kernel 0: split weights to fp16 hi/lo
// ---------------------------------------------------------------------------
__global__ __launch_bounds__(256) void wconv_kernel(const float* __restrict__ w1,
                                                    const float* __restrict__ w2) {
    int i = blockIdx.x * 256 + threadIdx.x;
    if (i < D_BOT * C_DIM) {
        __half h, l;
        split_h(w1[i], h, l);
        g_w1hi[i] = h; g_w1lo[i] = l;
        split_h(w2[i], h, l);
        g_w2hi[i] = h; g_w2lo[i] = l;
    }
}

// ---------------------------------------------------------------------------
// Kernel 1: dwconv 7x7 + bias + LN -> fp16 NHWC. Sliding-window registers.
// ---------------------------------------------------------------------------
#define DWLN_SBUF (8 * 2 * 7 * 72)          // floats
#define DWLN_SY   (64 * 129)
#define DWLN_SMEM ((DWLN_SBUF + DWLN_SY) * 4)

__global__ __launch_bounds__(256) void dwln_kernel(
    const float* __restrict__ x, const float* __restrict__ dw_w,
    const float* __restrict__ dw_b, const float* __restrict__ gamma,
    const float* __restrict__ beta)
{
    extern __shared__ float dyn[];
    float* s_buf = dyn;                 // [8 warps][2 ch][7 rows][72]
    float* s_y   = dyn + DWLN_SBUF;     // [64 w][129]

    const int bid = blockIdx.x;
    const int n = bid >> 6;
    const int h = bid & 63;
    const int tid = threadIdx.x;
    const int wg = tid >> 5;
    const int l  = tid & 31;
    const int half = l >> 4;
    const int li = l & 15;

    #pragma unroll 1
    for (int it = 0; it < 8; it++) {
        const int c = wg * 16 + it * 2 + half;
        float* rowbuf = s_buf + (size_t)(wg * 2 + half) * 7 * 72;
        #pragma unroll
        for (int dy = 0; dy < 7; dy++) {
            const int hh = h + dy - 3;
            float4 v = make_float4(0.f, 0.f, 0.f, 0.f);
            if (hh >= 0 && hh < H_DIM)
                v = *reinterpret_cast<const float4*>(
                    x + (((size_t)n * C_DIM + c) * H_DIM + hh) * W_DIM + 4 * li);
            float* rb = rowbuf + dy * 72;
            rb[3 + 4 * li] = v.x;
            rb[4 + 4 * li] = v.y;
            rb[5 + 4 * li] = v.z;
            rb[6 + 4 * li] = v.w;
            if (li == 0)  { rb[0] = 0.f; rb[1] = 0.f; rb[2] = 0.f; }
            if (li == 15) { rb[67] = 0.f; rb[68] = 0.f; rb[69] = 0.f; }
        }
        __syncwarp();

        const float bias = __ldg(&dw_b[c]);
        float acc[4] = {bias, bias, bias, bias};
        const float* wp = dw_w + c * 49;
        #pragma unroll
        for (int dy = 0; dy < 7; dy++) {
            const float* rb = rowbuf + dy * 72 + 4 * li;
            const float4 A = *reinterpret_cast<const float4*>(rb);
            const float4 B = *reinterpret_cast<const float4*>(rb + 4);
            const float2 Cc = *reinterpret_cast<const float2*>(rb + 8);
            const float v[10] = {A.x, A.y, A.z, A.w, B.x, B.y, B.z, B.w, Cc.x, Cc.y};
            #pragma unroll
            for (int dx = 0; dx < 7; dx++) {
                const float wv = __ldg(&wp[dy * 7 + dx]);
                acc[0] += v[dx]     * wv;
                acc[1] += v[dx + 1] * wv;
                acc[2] += v[dx + 2] * wv;
                acc[3] += v[dx + 3] * wv;
            }
        }
        #pragma unroll
        for (int j = 0; j < 4; j++)
            s_y[(4 * li + j) * 129 + c] = acc[j];
        __syncwarp();
    }
    __syncthreads();

    for (int wi = 0; wi < 8; wi++) {
        const int w = wg * 8 + wi;
        float v[4], s = 0.f, sq = 0.f;
        #pragma unroll
        for (int i = 0; i < 4; i++) {
            v[i] = s_y[w * 129 + l + 32 * i];
            s += v[i];
            sq += v[i] * v[i];
        }
        #pragma unroll
        for (int o = 16; o > 0; o >>= 1) {
            s  += __shfl_xor_sync(0xffffffffu, s, o);
            sq += __shfl_xor_sync(0xffffffffu, sq, o);
        }
        const float mu  = s * (1.f / 128.f);
        const float var = sq * (1.f / 128.f) - mu * mu;
        const float rs  = rsqrtf(var + EPS_LN);
        const size_t row = (((size_t)n * H_DIM + h) * W_DIM + w) * C_DIM;
        #pragma unroll
        for (int i = 0; i < 4; i++) {
            const int cix = l + 32 * i;
            const float val = (v[i] - mu) * rs * __ldg(&gamma[cix]) + __ldg(&beta[cix]);
            g_y[row + cix] = __float2half(val);
        }
    }
}

// ---------------------------------------------------------------------------
// mma.sync GEMM: CTA 128x128, 8 warps (2x4), warp tile 64x32, K-chunk 32.
// smem per buffer: A (act, single) + Whi + Wlo, each 128 rows x 80B. Dbl-buf.
// ---------------------------------------------------------------------------
#define ROW2   80
#define MAT2   (128 * ROW2)      // 10240 B
#define BUF2   (3 * MAT2)        // 30720 B
#define SMEM_G (2 * BUF2)        // 61440 B

__device__ __forceinline__ void stage3(
    const __half* __restrict__ A,
    const __half* __restrict__ Bh, const __half* __restrict__ Bl,
    int lda, int ldb, int arow0, int brow0, int k0, uint32_t buf)
{
    const int t = threadIdx.x;
    #pragma unroll
    for (int p = 0; p < 2; p++) {
        const int idx = p * 256 + t;          // 0..511
        const int row = idx >> 2, seg = idx & 3;
        const int koff = k0 + seg * 8;
        const uint32_t d = buf + row * ROW2 + seg * 16;
        cpasync16(d,            A  + (size_t)(arow0 + row) * lda + koff);
        cpasync16(d + MAT2,     Bh + (size_t)(brow0 + row) * ldb + koff);
        cpasync16(d + 2 * MAT2, Bl + (size_t)(brow0 + row) * ldb + koff);
    }
}

__device__ __forceinline__ void chunk2(uint32_t buf, int wm, int wn, int lane,
                                       float c[4][4][4])
{
    #pragma unroll
    for (int ks = 0; ks < 2; ks++) {
        const uint32_t aAddr = buf + (wm * 64 + (lane & 15)) * ROW2 +
                               ks * 32 + (lane >> 4) * 16;
        const uint32_t bAddr = buf + MAT2 +
                               (wn * 32 + (lane & 7) + (lane >> 4) * 8) * ROW2 +
                               ks * 32 + ((lane >> 3) & 1) * 16;
        uint32_t Af[4][4], Bh[2][4], Bl[2][4];
        #pragma unroll
        for (int mf = 0; mf < 4; mf++) ldsm4(Af[mf], aAddr + mf * (16 * ROW2));
        #pragma unroll
        for (int n2 = 0; n2 < 2; n2++) ldsm4(Bh[n2], bAddr + n2 * (16 * ROW2));
        #pragma unroll
        for (int mf = 0; mf < 4; mf++)
            #pragma unroll
            for (int nf = 0; nf < 4; nf++)
                mma_f16(c[mf][nf], Af[mf][0], Af[mf][1], Af[mf][2], Af[mf][3],
                        Bh[nf >> 1][(nf & 1) * 2], Bh[nf >> 1][(nf & 1) * 2 + 1]);
        #pragma unroll
        for (int n2 = 0; n2 < 2; n2++) ldsm4(Bl[n2], bAddr + MAT2 + n2 * (16 * ROW2));
        #pragma unroll
        for (int mf = 0; mf < 4; mf++)
            #pragma unroll
            for (int nf = 0; nf < 4; nf++)
                mma_f16(c[mf][nf], Af[mf][0], Af[mf][1], Af[mf][2], Af[mf][3],
                        Bl[nf >> 1][(nf & 1) * 2], Bl[nf >> 1][(nf & 1) * 2 + 1]);
    }
}

template <int NC>
__device__ __forceinline__ void run_gemm(
    const __half* A, const __half* Bh, const __half* Bl,
    int lda, int ldb, int arow0, int brow0, uint32_t sbase, float c[4][4][4])
{
    const int tid = threadIdx.x;
    const int wid = tid >> 5, lane = tid & 31;
    const int wm = wid >> 2, wn = wid & 3;

    stage3(A, Bh, Bl, lda, ldb, arow0, brow0, 0, sbase);
    asm volatile("cp.async.commit_group;");

    #pragma unroll 1
    for (int i = 0; i < NC; i++) {
        if (i + 1 < NC) {
            stage3(A, Bh, Bl, lda, ldb, arow0, brow0, (i + 1) * 32,
                   sbase + ((i + 1) & 1) * BUF2);
            asm volatile("cp.async.commit_group;");
            asm volatile("cp.async.wait_group 1;");
        } else {
            asm volatile("cp.async.wait_group 0;");
        }
        __syncthreads();
        chunk2(sbase + (i & 1) * BUF2, wm, wn, lane, c);
        __syncthreads();
    }
}

// ---------------------------------------------------------------------------
// Kernel 2: h = relu(y @ W1^T + b1) -> fp16
// ---------------------------------------------------------------------------
__global__ __launch_bounds__(256, 2) void gemm1_mma(const float* __restrict__ bias1)
{
    extern __shared__ char dsm[];
    float c[4][4][4];
    #pragma unroll
    for (int a = 0; a < 4; a++)
        #pragma unroll
        for (int b = 0; b < 4; b++)
            #pragma unroll
            for (int d = 0; d < 4; d++) c[a][b][d] = 0.f;

    const int j0 = blockIdx.x << 7;
    const int m0 = blockIdx.y << 7;

    run_gemm<4>(g_y, g_w1hi, g_w1lo, C_DIM, C_DIM, m0, j0, s2u(dsm), c);

    const int tid = threadIdx.x;
    const int wid = tid >> 5, lane = tid & 31;
    const int wm = wid >> 2, wn = wid & 3;
    const int r = lane >> 2, q = lane & 3;

    uint32_t* dh = (uint32_t*)g_h;
    #pragma unroll
    for (int nf = 0; nf < 4; nf++) {
        const int jc = j0 + wn * 32 + nf * 8 + 2 * q;
        const float2 bb = *reinterpret_cast<const float2*>(bias1 + jc);
        #pragma unroll
        for (int mf = 0; mf < 4; mf++)
            #pragma unroll
            for (int hf = 0; hf < 2; hf++) {
                const int row = m0 + wm * 64 + mf * 16 + r + 8 * hf;
                const float v0 = fmaxf(c[mf][nf][2 * hf]     + bb.x, 0.f);
                const float v1 = fmaxf(c[mf][nf][2 * hf + 1] + bb.y, 0.f);
                const size_t idx = (size_t)row * (D_BOT / 2) + (jc >> 1);
                dh[idx] = packh(__float2half(v0), __float2half(v1));
            }
    }
}

// ---------------------------------------------------------------------------
// Kernel 3: out = x + (h @ W2^T + b2), NCHW + residual
// ---------------------------------------------------------------------------
__global__ __launch_bounds__(256, 2) void gemm2_mma(const float* __restrict__ x,
                                                    const float* __restrict__ b2,
                                                    float* __restrict__ out)
{
    extern __shared__ char dsm[];
    float c[4][4][4];
    #pragma unroll
    for (int a = 0; a < 4; a++)
        #pragma unroll
        for (int b = 0; b < 4; b++)
            #pragma unroll
            for (int d = 0; d < 4; d++) c[a][b][d] = 0.f;

    const int m0 = blockIdx.x << 7;

    run_gemm<16>(g_h, g_w2hi, g_w2lo, D_BOT, D_BOT, m0, 0, s2u(dsm), c);

    const int tid = threadIdx.x;
    const int wid = tid >> 5, lane = tid & 31;
    const int wm = wid >> 2, wn = wid & 3;
    const int r = lane >> 2, q = lane & 3;

    float* sC = (float*)dsm;                  // 64 x 132 floats per half
    const int n  = m0 >> 12;
    const int sp0 = m0 & 4095;

    #pragma unroll 1
    for (int hh = 0; hh < 2; hh++) {
        if ((wn >> 1) == hh) {
            #pragma unroll
            for (int nf = 0; nf < 4; nf++) {
                const int cl = (wn & 1) * 32 + nf * 8 + 2 * q;
                #pragma unroll
                for (int mf = 0; mf < 4; mf++)
                    #pragma unroll
                    for (int hf = 0; hf < 2; hf++) {
                        const int ml = wm * 64 + mf * 16 + r + 8 * hf;
                        sC[cl * 132 + ml]       = c[mf][nf][2 * hf];
                        sC[(cl + 1) * 132 + ml] = c[mf][nf][2 * hf + 1];
                    }
            }
        }
        __syncthreads();
        #pragma unroll
        for (int qi = 0; qi < 8; qi++) {
            const int idx = qi * 256 + tid;
            const int j   = idx >> 5;
            const int m4  = (idx & 31) << 2;
            const int ch  = hh * 64 + j;
            const float bc = __ldg(&b2[ch]);
            const size_t g = ((size_t)(n * C_DIM + ch) << 12) + sp0 + m4;
            float4 v  = *reinterpret_cast<const float4*>(&sC[j * 132 + m4]);
            float4 xv = *reinterpret_cast<const float4*>(x + g);
            float4 o;
            o.x = v.x + xv.x + bc;
            o.y = v.y + xv.y + bc;
            o.z = v.z + xv.z + bc;
            o.w = v.w + xv.w + bc;
            *reinterpret_cast<float4*>(out + g) = o;
        }
        __syncthreads();
    }
}

// ---------------------------------------------------------------------------
extern "C" void kernel_launch(void* const* d_in, const int* in_sizes, int n_in,
                              void* d_out, int out_size)
{
    const float* x     = (const float*)d_in[0];
    const float* dw_w  = (const float*)d_in[1];
    const float* dw_b  = (const float*)d_in[2];
    const float* gamma = (const float*)d_in[3];
    const float* beta  = (const float*)d_in[4];
    const float* pw1_w = (const float*)d_in[5];
    const float* pw1_b = (const float*)d_in[6];
    const float* pw2_w = (const float*)d_in[7];
    const float* pw2_b = (const float*)d_in[8];
    float* out = (float*)d_out;

    static bool attr_done = false;
    if (!attr_done) {
        cudaFuncSetAttribute(dwln_kernel, cudaFuncAttributeMaxDynamicSharedMemorySize, DWLN_SMEM);
        cudaFuncSetAttribute(gemm1_mma, cudaFuncAttributeMaxDynamicSharedMemorySize, SMEM_G);
        cudaFuncSetAttribute(gemm2_mma, cudaFuncAttributeMaxDynamicSharedMemorySize, SMEM_G);
        attr_done = true;
    }

    wconv_kernel<<<(D_BOT * C_DIM + 255) / 256, 256>>>(pw1_w, pw2_w);
    dwln_kernel<<<N_IMG * H_DIM, 256, DWLN_SMEM>>>(x, dw_w, dw_b, gamma, beta);
    gemm1_mma<<<dim3(D_BOT / 128, M_TOT / 128), 256, SMEM_G>>>(pw1_b);
    gemm2_mma<<<M_TOT / 128, 256, SMEM_G>>>(x, pw2_b, out);
}